// round 3
// baseline (speedup 1.0000x reference)
#include <cuda_runtime.h>

// Problem constants (fixed by the reference)
constexpr int NN = 40000;   // nodes
constexpr int NE = 640000;  // edges
constexpr int DD = 128;     // feature dim
constexpr int NG = 64;      // graphs

constexpr int SCAN_B = 1024;
constexpr int NSCAN  = (NN + SCAN_B) / SCAN_B;  // 40 blocks, covers indices 0..NN inclusive

// ---------------- scratch (static device globals; no allocations) ----------------
__device__ float g_h  [NN * DD];   // scaled GEMM output: hs[r] = dinv[r] * (in @ W)[r]
__device__ float g_x2 [NN * DD];   // layer output buffer (layer-1 relu out, then layer-2 out)
__device__ int   g_deg[NN];        // in-degree (without self loop)
__device__ float g_dinv[NN];       // 1/sqrt(deg+1)
__device__ int   g_rowptr[NN + 1]; // CSR row pointers (by dst)
__device__ int   g_cnt[NN];        // fill cursors
__device__ int   g_csr[NE];        // CSR column indices (src node per edge)
__device__ int   g_bsum[NSCAN];    // scan block sums

// ---------------- CSR construction ----------------
__global__ void init_deg_kernel() {
    int i = blockIdx.x * blockDim.x + threadIdx.x;
    if (i < NN) g_deg[i] = 0;
}

__global__ void hist_kernel(const int* __restrict__ dst) {
    int i = blockIdx.x * blockDim.x + threadIdx.x;
    if (i < NE) atomicAdd(&g_deg[dst[i]], 1);
}

__global__ void scan1_kernel() {
    __shared__ int sh[SCAN_B];
    int tid = threadIdx.x;
    int i = blockIdx.x * SCAN_B + tid;
    int v = (i < NN) ? g_deg[i] : 0;
    sh[tid] = v;
    __syncthreads();
#pragma unroll
    for (int off = 1; off < SCAN_B; off <<= 1) {
        int t = (tid >= off) ? sh[tid - off] : 0;
        __syncthreads();
        sh[tid] += t;
        __syncthreads();
    }
    if (i <= NN) g_rowptr[i] = sh[tid] - v;  // exclusive within block
    if (tid == SCAN_B - 1) g_bsum[blockIdx.x] = sh[tid];
}

__global__ void scan2_kernel() {
    if (threadIdx.x == 0) {
        int s = 0;
        for (int b = 0; b < NSCAN; b++) {
            int t = g_bsum[b];
            g_bsum[b] = s;
            s += t;
        }
    }
}

__global__ void scan3_kernel() {
    int i = blockIdx.x * blockDim.x + threadIdx.x;
    if (i <= NN) {
        int rp = g_rowptr[i] + g_bsum[i / SCAN_B];
        g_rowptr[i] = rp;
        if (i < NN) {
            g_cnt[i]  = rp;
            g_dinv[i] = rsqrtf((float)(g_deg[i] + 1));  // +1: self loop
        }
    }
}

__global__ void fill_kernel(const int* __restrict__ src, const int* __restrict__ dst) {
    int i = blockIdx.x * blockDim.x + threadIdx.x;
    if (i < NE) {
        int slot = atomicAdd(&g_cnt[dst[i]], 1);
        g_csr[slot] = src[i];
    }
}

// ---------------- GEMM: g_h = dinv[row] * (A @ W) ----------------
// Block tile 128x128, 256 threads, 8x8 per thread, K-blocked by 16.
// SEL==0: A = param (the input x). SEL==1: A = g_x2.
template <int SEL>
__global__ void __launch_bounds__(256) gemm_kernel(const float* __restrict__ Ain,
                                                   const float* __restrict__ W) {
    const float* A = (SEL == 0) ? Ain : (const float*)g_x2;
    __shared__ float As[16][129];  // transposed A tile, padded (scalar reads)
    __shared__ float Bs[16][128];  // W tile

    int tid = threadIdx.x;
    int tx = tid & 15;    // 0..15 -> output cols tx*4 and tx*4+64
    int ty = tid >> 4;    // 0..15 -> output rows ty*8 .. ty*8+7
    int rowBase = blockIdx.x * 128;

    float acc[8][8];
#pragma unroll
    for (int i = 0; i < 8; i++)
#pragma unroll
        for (int j = 0; j < 8; j++) acc[i][j] = 0.f;

    for (int kt = 0; kt < 128; kt += 16) {
        // load A tile (128 rows x 16 k), transposed into As[k][m]
#pragma unroll
        for (int l = 0; l < 2; l++) {
            int idx = tid + l * 256;       // 0..511
            int r   = idx >> 2;            // 0..127
            int k4  = (idx & 3) << 2;      // 0,4,8,12
            float4 v = make_float4(0.f, 0.f, 0.f, 0.f);
            int gr = rowBase + r;
            if (gr < NN) v = *(const float4*)(A + gr * 128 + kt + k4);
            As[k4 + 0][r] = v.x;
            As[k4 + 1][r] = v.y;
            As[k4 + 2][r] = v.z;
            As[k4 + 3][r] = v.w;
        }
        // load W tile (16 k x 128 n)
#pragma unroll
        for (int l = 0; l < 2; l++) {
            int idx = tid + l * 256;
            int kk  = idx >> 5;            // 0..15
            int n4  = (idx & 31) << 2;     // 0..124
            *(float4*)&Bs[kk][n4] = *(const float4*)(W + (kt + kk) * 128 + n4);
        }
        __syncthreads();

#pragma unroll
        for (int k = 0; k < 16; k++) {
            float a[8], b[8];
#pragma unroll
            for (int i = 0; i < 8; i++) a[i] = As[k][ty * 8 + i];
            float4 b0 = *(const float4*)&Bs[k][tx * 4];
            float4 b1 = *(const float4*)&Bs[k][tx * 4 + 64];
            b[0] = b0.x; b[1] = b0.y; b[2] = b0.z; b[3] = b0.w;
            b[4] = b1.x; b[5] = b1.y; b[6] = b1.z; b[7] = b1.w;
#pragma unroll
            for (int i = 0; i < 8; i++)
#pragma unroll
                for (int j = 0; j < 8; j++) acc[i][j] = fmaf(a[i], b[j], acc[i][j]);
        }
        __syncthreads();
    }

    // epilogue: scale each row by dinv[row], store to g_h
#pragma unroll
    for (int i = 0; i < 8; i++) {
        int gr = rowBase + ty * 8 + i;
        if (gr < NN) {
            float s = g_dinv[gr];
            float4 o0 = make_float4(acc[i][0] * s, acc[i][1] * s, acc[i][2] * s, acc[i][3] * s);
            float4 o1 = make_float4(acc[i][4] * s, acc[i][5] * s, acc[i][6] * s, acc[i][7] * s);
            *(float4*)(g_h + gr * 128 + tx * 4)      = o0;
            *(float4*)(g_h + gr * 128 + tx * 4 + 64) = o1;
        }
    }
}

// ---------------- aggregation: warp per node ----------------
// out[i] = [relu]( dinv[i] * (hs[i] + sum_{j in N(i)} hs[j]) + bias )
template <bool RELU>
__global__ void __launch_bounds__(256) agg_kernel(const float* __restrict__ bias) {
    int w    = (blockIdx.x * blockDim.x + threadIdx.x) >> 5;
    int lane = threadIdx.x & 31;
    if (w >= NN) return;

    int beg = g_rowptr[w];
    int end = g_rowptr[w + 1];

    const float4* hv = (const float4*)g_h;
    float4 acc = hv[w * 32 + lane];  // self-loop term (already dinv-scaled)

    int k = beg;
    for (; k + 1 < end; k += 2) {
        int s0 = g_csr[k];
        int s1 = g_csr[k + 1];
        float4 v0 = hv[s0 * 32 + lane];
        float4 v1 = hv[s1 * 32 + lane];
        acc.x += v0.x; acc.y += v0.y; acc.z += v0.z; acc.w += v0.w;
        acc.x += v1.x; acc.y += v1.y; acc.z += v1.z; acc.w += v1.w;
    }
    if (k < end) {
        int s = g_csr[k];
        float4 v = hv[s * 32 + lane];
        acc.x += v.x; acc.y += v.y; acc.z += v.z; acc.w += v.w;
    }

    float dv = g_dinv[w];
    float4 bb = ((const float4*)bias)[lane];
    float4 r;
    r.x = fmaf(dv, acc.x, bb.x);
    r.y = fmaf(dv, acc.y, bb.y);
    r.z = fmaf(dv, acc.z, bb.z);
    r.w = fmaf(dv, acc.w, bb.w);
    if (RELU) {
        r.x = fmaxf(r.x, 0.f);
        r.y = fmaxf(r.y, 0.f);
        r.z = fmaxf(r.z, 0.f);
        r.w = fmaxf(r.w, 0.f);
    }
    ((float4*)g_x2)[w * 32 + lane] = r;
}

// ---------------- pooling: one block per graph (batch is sorted) ----------------
__device__ __forceinline__ int lower_bound_dev(const int* a, int n, int key) {
    int lo = 0, hi = n;
    while (lo < hi) {
        int mid = (lo + hi) >> 1;
        if (a[mid] < key) lo = mid + 1; else hi = mid;
    }
    return lo;
}

__global__ void pool_kernel(const int* __restrict__ batch, float* __restrict__ out) {
    __shared__ int s_lo, s_hi;
    int g = blockIdx.x;
    int t = threadIdx.x;  // 128 threads, one per feature
    if (t == 0) {
        s_lo = lower_bound_dev(batch, NN, g);
        s_hi = lower_bound_dev(batch, NN, g + 1);
    }
    __syncthreads();
    int lo = s_lo, hi = s_hi;
    float sum = 0.f;
    int r = lo;
    for (; r + 3 < hi; r += 4) {
        sum += g_x2[(r + 0) * 128 + t];
        sum += g_x2[(r + 1) * 128 + t];
        sum += g_x2[(r + 2) * 128 + t];
        sum += g_x2[(r + 3) * 128 + t];
    }
    for (; r < hi; r++) sum += g_x2[r * 128 + t];
    float c = (float)(hi - lo);
    out[g * 128 + t] = sum / fmaxf(c, 1.0f);
}

// ---------------- launch ----------------
extern "C" void kernel_launch(void* const* d_in, const int* in_sizes, int n_in,
                              void* d_out, int out_size) {
    const float* x     = (const float*)d_in[0];
    const int*   ei    = (const int*)d_in[1];   // [2, E] row-major
    const int*   batch = (const int*)d_in[2];
    const float* W1    = (const float*)d_in[3];
    const float* b1    = (const float*)d_in[4];
    const float* W2    = (const float*)d_in[5];
    const float* b2    = (const float*)d_in[6];
    float* out = (float*)d_out;

    const int* src = ei;        // edge_index[0]
    const int* dst = ei + NE;   // edge_index[1]

    // CSR build (by destination) + dinv
    init_deg_kernel<<<(NN + 255) / 256, 256>>>();
    hist_kernel<<<(NE + 255) / 256, 256>>>(dst);
    scan1_kernel<<<NSCAN, SCAN_B>>>();
    scan2_kernel<<<1, 32>>>();
    scan3_kernel<<<(NN + 1 + 255) / 256, 256>>>();
    fill_kernel<<<(NE + 255) / 256, 256>>>(src, dst);

    // Layer 1: hs = dinv * (x @ W1); x2 = relu(dinv*(hs_self + sum hs_nbr) + b1)
    gemm_kernel<0><<<(NN + 127) / 128, 256>>>(x, W1);
    agg_kernel<true><<<(NN + 7) / 8, 256>>>(b1);

    // Layer 2: hs = dinv * (x2 @ W2); x2 = dinv*(hs_self + sum hs_nbr) + b2
    gemm_kernel<1><<<(NN + 127) / 128, 256>>>(x, W2);
    agg_kernel<false><<<(NN + 7) / 8, 256>>>(b2);

    // Global mean pool
    pool_kernel<<<NG, DD>>>(batch, out);
}

// round 4
// speedup vs baseline: 1.7187x; 1.7187x over previous
#include <cuda_runtime.h>

// Problem constants (fixed by the reference)
constexpr int NN = 40000;   // nodes
constexpr int NE = 640000;  // edges
constexpr int DD = 128;     // feature dim
constexpr int NG = 64;      // graphs

constexpr int SCAN_B = 1024;
constexpr int NSCAN  = (NN + SCAN_B) / SCAN_B;  // 40 blocks, covers indices 0..NN inclusive

// ---------------- scratch (static device globals; no allocations) ----------------
__device__ float g_h  [NN * DD];   // scaled GEMM output: hs[r] = dinv[r] * (in @ W)[r]
__device__ float g_x2 [NN * DD];   // layer output buffer
__device__ int   g_deg[NN];        // in-degree (without self loop)
__device__ float g_dinv[NN];       // 1/sqrt(deg+1)
__device__ int   g_rowptr[NN + 1]; // CSR row pointers (by dst)
__device__ int   g_cnt[NN];        // fill cursors
__device__ int   g_csr[NE];        // CSR column indices (src node per edge)
__device__ int   g_bsum[64];       // scan block sums (NSCAN=40 used)

// ---------------- packed f32x2 helpers ----------------
__device__ __forceinline__ unsigned long long pack2(float lo, float hi) {
    unsigned long long r;
    asm("mov.b64 %0, {%1, %2};" : "=l"(r) : "f"(lo), "f"(hi));
    return r;
}
__device__ __forceinline__ void unpack2(unsigned long long v, float& lo, float& hi) {
    asm("mov.b64 {%0, %1}, %2;" : "=f"(lo), "=f"(hi) : "l"(v));
}
__device__ __forceinline__ unsigned long long fma2(unsigned long long a,
                                                   unsigned long long b,
                                                   unsigned long long c) {
    unsigned long long d;
    asm("fma.rn.f32x2 %0, %1, %2, %3;" : "=l"(d) : "l"(a), "l"(b), "l"(c));
    return d;
}

// ---------------- CSR construction ----------------
__global__ void init_deg_kernel() {
    int i = blockIdx.x * blockDim.x + threadIdx.x;
    if (i < NN) g_deg[i] = 0;
}

__global__ void hist_kernel(const int* __restrict__ dst) {
    int i = blockIdx.x * blockDim.x + threadIdx.x;
    if (i < NE) atomicAdd(&g_deg[dst[i]], 1);
}

__global__ void scan1_kernel() {
    __shared__ int sh[SCAN_B];
    int tid = threadIdx.x;
    int i = blockIdx.x * SCAN_B + tid;
    int v = (i < NN) ? g_deg[i] : 0;
    sh[tid] = v;
    __syncthreads();
#pragma unroll
    for (int off = 1; off < SCAN_B; off <<= 1) {
        int t = (tid >= off) ? sh[tid - off] : 0;
        __syncthreads();
        sh[tid] += t;
        __syncthreads();
    }
    if (i <= NN) g_rowptr[i] = sh[tid] - v;  // exclusive within block
    if (tid == SCAN_B - 1) g_bsum[blockIdx.x] = sh[tid];
}

// Parallel scan of the 40 block sums: 2 warps, shuffle scan + cross-warp fixup.
__global__ void scan2_kernel() {
    int t = threadIdx.x;           // 64 threads
    int lane = t & 31;
    int wrp = t >> 5;
    int v = (t < NSCAN) ? g_bsum[t] : 0;
    int inc = v;
#pragma unroll
    for (int off = 1; off < 32; off <<= 1) {
        int n = __shfl_up_sync(0xFFFFFFFFu, inc, off);
        if (lane >= off) inc += n;
    }
    __shared__ int wtot;
    if (wrp == 0 && lane == 31) wtot = inc;
    __syncthreads();
    if (wrp == 1) inc += wtot;
    if (t < NSCAN) g_bsum[t] = inc - v;  // exclusive
}

__global__ void scan3_kernel() {
    int i = blockIdx.x * blockDim.x + threadIdx.x;
    if (i <= NN) {
        int rp = g_rowptr[i] + g_bsum[i / SCAN_B];
        g_rowptr[i] = rp;
        if (i < NN) {
            g_cnt[i]  = rp;
            g_dinv[i] = rsqrtf((float)(g_deg[i] + 1));  // +1: self loop
        }
    }
}

__global__ void fill_kernel(const int* __restrict__ src, const int* __restrict__ dst) {
    int i = blockIdx.x * blockDim.x + threadIdx.x;
    if (i < NE) {
        int slot = atomicAdd(&g_cnt[dst[i]], 1);
        g_csr[slot] = src[i];
    }
}

// ---------------- GEMM: g_h = dinv[row] * (A @ W) ----------------
// Block tile 128x128, 256 threads, 8x8 per thread, K-blocked by 16.
// Mainloop uses packed fma.rn.f32x2 (2 FLOP-pairs per issued instruction).
// SEL==0: A = param (the input x). SEL==1: A = g_x2.
template <int SEL>
__global__ void __launch_bounds__(256) gemm_kernel(const float* __restrict__ Ain,
                                                   const float* __restrict__ W) {
    const float* A = (SEL == 0) ? Ain : (const float*)g_x2;
    __shared__ float As[16][132];  // transposed A tile; stride 132 keeps 16B alignment
    __shared__ float Bs[16][128];  // W tile

    int tid = threadIdx.x;
    int tx = tid & 15;    // output cols tx*4..+3 and tx*4+64..+3
    int ty = tid >> 4;    // output rows ty*8..+7
    int rowBase = blockIdx.x * 128;

    unsigned long long acc2[8][4];
    const unsigned long long zz = 0ull;
#pragma unroll
    for (int i = 0; i < 8; i++)
#pragma unroll
        for (int j = 0; j < 4; j++) acc2[i][j] = zz;

    for (int kt = 0; kt < 128; kt += 16) {
        // load A tile (128 rows x 16 k), transposed into As[k][m]
#pragma unroll
        for (int l = 0; l < 2; l++) {
            int idx = tid + l * 256;       // 0..511
            int r   = idx >> 2;            // 0..127
            int k4  = (idx & 3) << 2;      // 0,4,8,12
            float4 v = make_float4(0.f, 0.f, 0.f, 0.f);
            int gr = rowBase + r;
            if (gr < NN) v = *(const float4*)(A + gr * 128 + kt + k4);
            As[k4 + 0][r] = v.x;
            As[k4 + 1][r] = v.y;
            As[k4 + 2][r] = v.z;
            As[k4 + 3][r] = v.w;
        }
        // load W tile (16 k x 128 n)
#pragma unroll
        for (int l = 0; l < 2; l++) {
            int idx = tid + l * 256;
            int kk  = idx >> 5;            // 0..15
            int n4  = (idx & 31) << 2;     // 0..124
            *(float4*)&Bs[kk][n4] = *(const float4*)(W + (kt + kk) * 128 + n4);
        }
        __syncthreads();

#pragma unroll
        for (int k = 0; k < 16; k++) {
            // a: 8 contiguous floats (two LDS.128), duplicated into f32x2 lanes
            float4 a0 = *(const float4*)&As[k][ty * 8];
            float4 a1 = *(const float4*)&As[k][ty * 8 + 4];
            unsigned long long ad[8];
            ad[0] = pack2(a0.x, a0.x); ad[1] = pack2(a0.y, a0.y);
            ad[2] = pack2(a0.z, a0.z); ad[3] = pack2(a0.w, a0.w);
            ad[4] = pack2(a1.x, a1.x); ad[5] = pack2(a1.y, a1.y);
            ad[6] = pack2(a1.z, a1.z); ad[7] = pack2(a1.w, a1.w);
            // b: 8 floats as 4 packed f32x2 (two LDS.128)
            ulonglong2 bp0 = *(const ulonglong2*)&Bs[k][tx * 4];
            ulonglong2 bp1 = *(const ulonglong2*)&Bs[k][tx * 4 + 64];
            unsigned long long bd[4] = {bp0.x, bp0.y, bp1.x, bp1.y};
#pragma unroll
            for (int i = 0; i < 8; i++)
#pragma unroll
                for (int j = 0; j < 4; j++)
                    acc2[i][j] = fma2(ad[i], bd[j], acc2[i][j]);
        }
        __syncthreads();
    }

    // epilogue: scale each row by dinv[row], store to g_h
#pragma unroll
    for (int i = 0; i < 8; i++) {
        int gr = rowBase + ty * 8 + i;
        if (gr < NN) {
            float s = g_dinv[gr];
            float o[8];
#pragma unroll
            for (int j = 0; j < 4; j++) {
                float lo, hi;
                unpack2(acc2[i][j], lo, hi);
                o[2 * j]     = lo * s;
                o[2 * j + 1] = hi * s;
            }
            *(float4*)(g_h + gr * 128 + tx * 4)      = make_float4(o[0], o[1], o[2], o[3]);
            *(float4*)(g_h + gr * 128 + tx * 4 + 64) = make_float4(o[4], o[5], o[6], o[7]);
        }
    }
}

// ---------------- aggregation: warp per node ----------------
// out[i] = [relu]( dinv[i] * (hs[i] + sum_{j in N(i)} hs[j]) + bias )
template <bool RELU>
__global__ void __launch_bounds__(256) agg_kernel(const float* __restrict__ bias) {
    int w    = (blockIdx.x * blockDim.x + threadIdx.x) >> 5;
    int lane = threadIdx.x & 31;
    if (w >= NN) return;

    int beg = g_rowptr[w];
    int end = g_rowptr[w + 1];

    const float4* hv = (const float4*)g_h;
    float4 acc = hv[w * 32 + lane];  // self-loop term (already dinv-scaled)

    int k = beg;
    for (; k + 3 < end; k += 4) {
        int s0 = g_csr[k];
        int s1 = g_csr[k + 1];
        int s2 = g_csr[k + 2];
        int s3 = g_csr[k + 3];
        float4 v0 = hv[s0 * 32 + lane];
        float4 v1 = hv[s1 * 32 + lane];
        float4 v2 = hv[s2 * 32 + lane];
        float4 v3 = hv[s3 * 32 + lane];
        acc.x += v0.x; acc.y += v0.y; acc.z += v0.z; acc.w += v0.w;
        acc.x += v1.x; acc.y += v1.y; acc.z += v1.z; acc.w += v1.w;
        acc.x += v2.x; acc.y += v2.y; acc.z += v2.z; acc.w += v2.w;
        acc.x += v3.x; acc.y += v3.y; acc.z += v3.z; acc.w += v3.w;
    }
    for (; k < end; k++) {
        int s = g_csr[k];
        float4 v = hv[s * 32 + lane];
        acc.x += v.x; acc.y += v.y; acc.z += v.z; acc.w += v.w;
    }

    float dv = g_dinv[w];
    float4 bb = ((const float4*)bias)[lane];
    float4 r;
    r.x = fmaf(dv, acc.x, bb.x);
    r.y = fmaf(dv, acc.y, bb.y);
    r.z = fmaf(dv, acc.z, bb.z);
    r.w = fmaf(dv, acc.w, bb.w);
    if (RELU) {
        r.x = fmaxf(r.x, 0.f);
        r.y = fmaxf(r.y, 0.f);
        r.z = fmaxf(r.z, 0.f);
        r.w = fmaxf(r.w, 0.f);
    }
    ((float4*)g_x2)[w * 32 + lane] = r;
}

// ---------------- pooling: one block per graph, 512 threads ----------------
__device__ __forceinline__ int lower_bound_dev(const int* a, int n, int key) {
    int lo = 0, hi = n;
    while (lo < hi) {
        int mid = (lo + hi) >> 1;
        if (a[mid] < key) lo = mid + 1; else hi = mid;
    }
    return lo;
}

__global__ void __launch_bounds__(512) pool_kernel(const int* __restrict__ batch,
                                                   float* __restrict__ out) {
    __shared__ int s_lo, s_hi;
    __shared__ float red[4][128];
    int g = blockIdx.x;
    int t = threadIdx.x;
    int f   = t & 127;   // feature
    int seg = t >> 7;    // row slice 0..3
    if (t == 0) {
        s_lo = lower_bound_dev(batch, NN, g);
        s_hi = lower_bound_dev(batch, NN, g + 1);
    }
    __syncthreads();
    int lo = s_lo, hi = s_hi;
    float sum = 0.f;
    for (int r = lo + seg; r < hi; r += 4) sum += g_x2[r * 128 + f];
    red[seg][f] = sum;
    __syncthreads();
    if (seg == 0) {
        float c = (float)(hi - lo);
        float tot = red[0][f] + red[1][f] + red[2][f] + red[3][f];
        out[g * 128 + f] = tot / fmaxf(c, 1.0f);
    }
}

// ---------------- launch ----------------
extern "C" void kernel_launch(void* const* d_in, const int* in_sizes, int n_in,
                              void* d_out, int out_size) {
    const float* x     = (const float*)d_in[0];
    const int*   ei    = (const int*)d_in[1];   // [2, E] row-major
    const int*   batch = (const int*)d_in[2];
    const float* W1    = (const float*)d_in[3];
    const float* b1    = (const float*)d_in[4];
    const float* W2    = (const float*)d_in[5];
    const float* b2    = (const float*)d_in[6];
    float* out = (float*)d_out;

    const int* src = ei;        // edge_index[0]
    const int* dst = ei + NE;   // edge_index[1]

    // CSR build (by destination) + dinv
    init_deg_kernel<<<(NN + 255) / 256, 256>>>();
    hist_kernel<<<(NE + 255) / 256, 256>>>(dst);
    scan1_kernel<<<NSCAN, SCAN_B>>>();
    scan2_kernel<<<1, 64>>>();
    scan3_kernel<<<(NN + 1 + 255) / 256, 256>>>();
    fill_kernel<<<(NE + 255) / 256, 256>>>(src, dst);

    // Layer 1: hs = dinv * (x @ W1); x2 = relu(dinv*(hs_self + sum hs_nbr) + b1)
    gemm_kernel<0><<<(NN + 127) / 128, 256>>>(x, W1);
    agg_kernel<true><<<(NN + 7) / 8, 256>>>(b1);

    // Layer 2: hs = dinv * (x2 @ W2); x2 = dinv*(hs_self + sum hs_nbr) + b2
    gemm_kernel<1><<<(NN + 127) / 128, 256>>>(x, W2);
    agg_kernel<false><<<(NN + 7) / 8, 256>>>(b2);

    // Global mean pool
    pool_kernel<<<NG, 512>>>(batch, out);
}